// round 10
// baseline (speedup 1.0000x reference)
#include <cuda_runtime.h>
#include <cuda_fp16.h>
#include <cstdint>

// ============================================================================
// Sizes
// ============================================================================
#define MDIM 16384
#define NDIM 2048
#define KDIM 2048

#define BM 128
#define BN 256
#define BK 32
#define NK (KDIM / BK)            // 64 k-chunks
#define NTILES (NDIM / BN)        // 8
#define MTILES (MDIM / BM)        // 128
#define GRID_CTAS (MTILES * NTILES)  // 1024

// Static SMEM, 2 stages: per stage A 128x64B = 8192B, B 256x64B = 16384B.
// Stage = 24576B, total = 49152B = 48KB exactly (static limit; dynamic-smem
// attribute path kills the harness container).
// Rows are 64B (32 halfs) with XOR swizzle: 16B chunk' = chunk ^ ((row>>1)&3).
#define A_TILE_BYTES 8192
#define B_TILE_BYTES 16384
#define STAGE_BYTES  24576
#define SMEM_TOTAL   49152

// ============================================================================
// Static scratch (sanctioned no-alloc path) -- only W_eff now; x is consumed
// directly as fp32 by the GEMM loader (inline conversion).
// ============================================================================
__device__ __align__(256) __half g_wh[(size_t)NDIM * KDIM];   // 8 MB

// ============================================================================
// Helpers
// ============================================================================
__device__ __forceinline__ uint32_t smem_u32(const void* p) {
    uint32_t a;
    asm("{ .reg .u64 t; cvta.to.shared.u64 t, %1; cvt.u32.u64 %0, t; }" : "=r"(a) : "l"(p));
    return a;
}

__device__ __forceinline__ void cp_async16(uint32_t dst_smem, const void* src) {
    asm volatile("cp.async.cg.shared.global [%0], [%1], 16;" :: "r"(dst_smem), "l"(src) : "memory");
}
#define CP_COMMIT() asm volatile("cp.async.commit_group;" ::: "memory")
#define CP_WAIT(n)  asm volatile("cp.async.wait_group %0;" :: "n"(n) : "memory")

__device__ __forceinline__ void mma16816(float* d, const uint32_t* a, const uint32_t* b) {
    asm volatile(
        "mma.sync.aligned.m16n8k16.row.col.f32.f16.f16.f32 "
        "{%0,%1,%2,%3}, {%4,%5,%6,%7}, {%8,%9}, {%0,%1,%2,%3};"
        : "+f"(d[0]), "+f"(d[1]), "+f"(d[2]), "+f"(d[3])
        : "r"(a[0]), "r"(a[1]), "r"(a[2]), "r"(a[3]), "r"(b[0]), "r"(b[1]));
}

// swizzled byte offset of a 16B chunk within a 64B-pitch tile
__device__ __forceinline__ int swz_off(int row, int chunk) {
    return row * 64 + ((chunk ^ ((row >> 1) & 3)) << 4);
}

// ============================================================================
// Phase 1: W_eff = weight + sum_r kron(L0_r,L1_r,L2_r)[:2048,:2048]  -> fp16
// ============================================================================
__global__ void __launch_bounds__(256) prep_w_kernel(const float* __restrict__ weight,
                                                     const float* __restrict__ leaf) {
    int idx = blockIdx.x * 256 + threadIdx.x;   // exactly NDIM*KDIM threads
    int n = idx >> 11;
    int k = idx & 2047;
    int n1 = n / 169; int nr = n - n1 * 169; int n2 = nr / 13; int n3 = nr - n2 * 13;
    int k1 = k / 169; int kr = k - k1 * 169; int k2 = kr / 13; int k3 = kr - k2 * 13;
    float d = 0.f;
#pragma unroll
    for (int r = 0; r < 4; r++) {
        float a = __ldg(&leaf[((0 * 4 + r) * 13 + n1) * 13 + k1]);
        float b = __ldg(&leaf[((1 * 4 + r) * 13 + n2) * 13 + k2]);
        float c = __ldg(&leaf[((2 * 4 + r) * 13 + n3) * 13 + k3]);
        d += a * b * c;
    }
    g_wh[idx] = __float2half(weight[idx] + d);
}

// ============================================================================
// Phase 2: GEMM  y = x @ W_eff^T + bias   (fp16 HMMA, fp32 accum)
// CTA 128x256, 8 warps (2x4), warp tile 64x64, BK=32, 2-stage pipeline,
// 48KB static smem, XOR-swizzled 64B rows, scalar LDS fragment loads
// (measured fastest; tensor pipe is the binding resource).
// A is read as fp32 from the input and converted inline (LDG->cvt->STS),
// eliminating the separate convert_x pass. B arrives via cp.async.
// ============================================================================
__global__ void __launch_bounds__(256, 1)
gemm_kernel(const float* __restrict__ x, const float* __restrict__ bias,
            float* __restrict__ out)
{
    __shared__ __align__(16) char smem[SMEM_TOTAL];
    const uint32_t sb = smem_u32(smem);
    const int tid = threadIdx.x;
    const int lane = tid & 31;
    const int wid = tid >> 5;
    const int wm = wid >> 2;           // 0..1  (64-row half)
    const int wn = wid & 3;            // 0..3  (64-col quarter)
    const int r1 = lane >> 2;          // 0..7
    const int c0 = (lane & 3) * 2;     // 0,2,4,6

    const int ntile = (int)blockIdx.x & (NTILES - 1);
    const int mtile = (int)blockIdx.x >> 3;
    const int m0 = mtile * BM;
    const int n0 = ntile * BN;

    const float* gAx = x + (size_t)m0 * KDIM;
    const __half* gB = g_wh + (size_t)n0 * KDIM;

    // ---- A staging: thread handles chunks c=tid and c=tid+256 of 512 ----
    // chunk c -> row = c>>2 (0..127), k8 = c&3 (16B half-chunk = 8 halfs)
    const int arow0 = tid >> 2;
    const int arow1 = (tid + 256) >> 2;
    const int ak8 = tid & 3;                    // same for both
    const float* asrc0 = gAx + (size_t)arow0 * KDIM + ak8 * 8;
    const float* asrc1 = gAx + (size_t)arow1 * KDIM + ak8 * 8;
    const uint32_t adst0 = sb + swz_off(arow0, ak8);
    const uint32_t adst1 = sb + swz_off(arow1, ak8);

    float4 ar[2][2];   // staged fp32 A data for the NEXT chunk to be stored

    auto ldgA = [&](int kc) {
        const float* p0 = asrc0 + kc * BK;
        const float* p1 = asrc1 + kc * BK;
        ar[0][0] = __ldg((const float4*)p0);
        ar[0][1] = __ldg((const float4*)(p0 + 4));
        ar[1][0] = __ldg((const float4*)p1);
        ar[1][1] = __ldg((const float4*)(p1 + 4));
    };
    auto stsA = [&](int s) {
        const uint32_t off = (uint32_t)s * STAGE_BYTES;
#pragma unroll
        for (int i = 0; i < 2; i++) {
            __half2 h0 = __floats2half2_rn(ar[i][0].x, ar[i][0].y);
            __half2 h1 = __floats2half2_rn(ar[i][0].z, ar[i][0].w);
            __half2 h2 = __floats2half2_rn(ar[i][1].x, ar[i][1].y);
            __half2 h3 = __floats2half2_rn(ar[i][1].z, ar[i][1].w);
            uint32_t u0 = *(uint32_t*)&h0, u1 = *(uint32_t*)&h1;
            uint32_t u2 = *(uint32_t*)&h2, u3 = *(uint32_t*)&h3;
            uint32_t d = (i ? adst1 : adst0) + off;
            asm volatile("st.shared.v4.b32 [%0], {%1,%2,%3,%4};"
                :: "r"(d), "r"(u0), "r"(u1), "r"(u2), "r"(u3) : "memory");
        }
    };
    auto loadB = [&](int kc, int s) {
        uint32_t sB = sb + s * STAGE_BYTES + A_TILE_BYTES;
        int koff = kc * BK;
#pragma unroll
        for (int i = 0; i < 4; i++) {
            int c = tid + 256 * i;           // 0..1023
            int row = c >> 2, k8 = c & 3;
            cp_async16(sB + swz_off(row, k8), gB + (size_t)row * KDIM + koff + k8 * 8);
        }
        CP_COMMIT();
    };

    float acc[4][8][4];
#pragma unroll
    for (int i = 0; i < 4; i++)
#pragma unroll
        for (int j = 0; j < 8; j++)
#pragma unroll
            for (int q = 0; q < 4; q++) acc[i][j][q] = 0.f;

    // ---- prologue ----
    ldgA(0); stsA(0);          // A(0) -> stage 0 (direct STS)
    loadB(0, 0);               // B(0) -> stage 0 (async, group 0)
    ldgA(1);                   // A(1) -> regs (stored at top of iter 0)

    for (int kc = 0; kc < NK; kc++) {
        if (kc + 1 < NK) {
            stsA((kc + 1) & 1);             // A(kc+1) into buffer freed by iter kc-1's barrier
            loadB(kc + 1, (kc + 1) & 1);    // B(kc+1) async
        }
        {   // prefetch A(kc+2) fp32 into regs (latency hidden under compute)
            int kc2 = (kc + 2 < NK) ? kc + 2 : NK - 1;
            ldgA(kc2);
        }
        if (kc + 1 < NK) { CP_WAIT(1); } else { CP_WAIT(0); }   // B(kc) arrived
        __syncthreads();    // B(kc) + A(kc) visible to all warps

        const char* sa = smem + (kc & 1) * STAGE_BYTES;
        const char* sB = sa + A_TILE_BYTES;

#pragma unroll
        for (int kk = 0; kk < BK; kk += 16) {
            const int byte0 = (kk + c0) * 2;       // 0..12 | 32..44
            const int ch0 = byte0 >> 4;            // 0 | 2
            const int w0 = byte0 & 15;

            uint32_t a[4][4];
            uint32_t b[8][2];
#pragma unroll
            for (int ma = 0; ma < 4; ma++) {
                int row = wm * 64 + ma * 16 + r1;
                int s = (row >> 1) & 3;            // same for row and row+8
                int o0 = row * 64 + ((ch0 ^ s) << 4) + w0;
                int o2 = row * 64 + (((ch0 + 1) ^ s) << 4) + w0;
                a[ma][0] = *(const uint32_t*)(sa + o0);
                a[ma][1] = *(const uint32_t*)(sa + o0 + 512);    // +8 rows
                a[ma][2] = *(const uint32_t*)(sa + o2);
                a[ma][3] = *(const uint32_t*)(sa + o2 + 512);
            }
#pragma unroll
            for (int nb = 0; nb < 8; nb++) {
                int row = wn * 64 + nb * 8 + r1;
                int s = (row >> 1) & 3;
                b[nb][0] = *(const uint32_t*)(sB + row * 64 + ((ch0 ^ s) << 4) + w0);
                b[nb][1] = *(const uint32_t*)(sB + row * 64 + (((ch0 + 1) ^ s) << 4) + w0);
            }
#pragma unroll
            for (int ma = 0; ma < 4; ma++)
#pragma unroll
                for (int nb = 0; nb < 8; nb++)
                    mma16816(acc[ma][nb], a[ma], b[nb]);
        }
        __syncthreads();   // all warps done with buffer kc&1 before refill
    }

    // ---- epilogue: + bias, fp32 out ----
#pragma unroll
    for (int ma = 0; ma < 4; ma++) {
        int row0 = m0 + wm * 64 + ma * 16 + r1;
        float* orow0 = out + (size_t)row0 * NDIM;
        float* orow1 = orow0 + (size_t)8 * NDIM;
#pragma unroll
        for (int nb = 0; nb < 8; nb++) {
            int col = n0 + wn * 64 + nb * 8 + c0;
            float bv0 = __ldg(&bias[col]);
            float bv1 = __ldg(&bias[col + 1]);
            float2 v0 = make_float2(acc[ma][nb][0] + bv0, acc[ma][nb][1] + bv1);
            float2 v1 = make_float2(acc[ma][nb][2] + bv0, acc[ma][nb][3] + bv1);
            *reinterpret_cast<float2*>(orow0 + col) = v0;
            *reinterpret_cast<float2*>(orow1 + col) = v1;
        }
    }
}

// ============================================================================
// Host: kernel launches only -- no attribute calls, no allocation, no sync.
// ============================================================================
extern "C" void kernel_launch(void* const* d_in, const int* in_sizes, int n_in,
                              void* d_out, int out_size) {
    // Identify inputs by element count (robust to metadata ordering).
    const float* x = nullptr;
    const float* leaf = nullptr;
    const float* weight = nullptr;
    const float* bias = nullptr;
    for (int i = 0; i < n_in; i++) {
        switch (in_sizes[i]) {
            case 2028:     leaf   = (const float*)d_in[i]; break;  // 3*4*13*13
            case 2048:     bias   = (const float*)d_in[i]; break;
            case 4194304:  weight = (const float*)d_in[i]; break;  // 2048*2048
            default:       x      = (const float*)d_in[i]; break;  // 8*2048*2048
        }
    }
    float* out = (float*)d_out;

    prep_w_kernel<<<(NDIM * KDIM) / 256, 256>>>(weight, leaf);
    gemm_kernel<<<GRID_CTAS, 256>>>(x, bias, out);
}